// round 16
// baseline (speedup 1.0000x reference)
#include <cuda_runtime.h>
#include <cuda_bf16.h>
#include <math.h>

#define NB 4
#define NN 2048
#define PIN 256
#define POUT 128
#define FIN 512
#define FOUT 128
#define KH 32

typedef unsigned long long ull;
typedef unsigned int u32;

// ---------------- scratch (device globals) ----------------
__device__ float g_x [2][NB][NN][POUT];
__device__ float g_xh[2][NB][NN][POUT];     // normal layout (s1/s2 epilogue)
__device__ float g_xhp[2][NB][NN][POUT];    // permuted: d = h*32 + rr*4 + ng
__device__ float g_s1[2][NB][NN][4];
__device__ float g_s2[2][NB][NN][4];
__device__ float g_G [2][NB][NN][POUT];
__device__ float g_h [2][NB][FOUT];
__device__ float g_gpart[2][NB][8][132];

// ---------------- f32x2 helpers (SIMT GEMMs) ----------------
__device__ __forceinline__ ull ffma2(ull a, ull b, ull c) {
    ull d; asm("fma.rn.f32x2 %0, %1, %2, %3;" : "=l"(d) : "l"(a), "l"(b), "l"(c)); return d;
}
__device__ __forceinline__ ull pack2(float v) {
    ull r; asm("mov.b64 %0, {%1, %1};" : "=l"(r) : "f"(v)); return r;
}
__device__ __forceinline__ float2 unpack2(ull v) {
    float2 r; asm("mov.b64 {%0, %1}, %2;" : "=f"(r.x), "=f"(r.y) : "l"(v)); return r;
}

// ---------------- tf32 warp mma ----------
__device__ __forceinline__ void mma1688(float* d, float a0, float a1, float a2, float a3,
                                        float b0, float b1) {
    asm volatile(
        "mma.sync.aligned.m16n8k8.row.col.f32.tf32.tf32.f32 "
        "{%0,%1,%2,%3}, {%4,%5,%6,%7}, {%8,%9}, {%0,%1,%2,%3};"
        : "+f"(d[0]), "+f"(d[1]), "+f"(d[2]), "+f"(d[3])
        : "r"(__float_as_uint(a0)), "r"(__float_as_uint(a1)),
          "r"(__float_as_uint(a2)), "r"(__float_as_uint(a3)),
          "r"(__float_as_uint(b0)), "r"(__float_as_uint(b1)));
}

// ---------------- GEMM: C[M,128] = A[M,KC] @ W[128,KC]^T + bias ----------------
template<int KC>
__device__ __forceinline__ void gemm_body(const float* __restrict__ A,
                                          const float* __restrict__ W,
                                          const float* __restrict__ bias,
                                          float* __restrict__ C)
{
    __shared__ float As[32][72];
    __shared__ float Ws[32][132];
    int t = threadIdx.x;
    int r0 = blockIdx.x * 64;
    int rr = (t >> 5) * 8;
    int cc = (t & 31) * 4;

    ull acc[4][4];
#pragma unroll
    for (int j = 0; j < 4; ++j)
#pragma unroll
        for (int c = 0; c < 4; ++c) acc[j][c] = 0ull;

    for (int kt = 0; kt < KC; kt += 32) {
        __syncthreads();
#pragma unroll
        for (int q = 0; q < 2; ++q) {
            int idx = t + 256 * q;
            int row = idx >> 3, kq = (idx & 7) * 4;
            float4 v = *reinterpret_cast<const float4*>(&A[(size_t)(r0 + row) * KC + kt + kq]);
            As[kq][row] = v.x; As[kq + 1][row] = v.y; As[kq + 2][row] = v.z; As[kq + 3][row] = v.w;
        }
#pragma unroll
        for (int q = 0; q < 4; ++q) {
            int idx = t + 256 * q;
            int c = idx >> 3, kq = (idx & 7) * 4;
            float4 v = *reinterpret_cast<const float4*>(&W[(size_t)c * KC + kt + kq]);
            Ws[kq][c] = v.x; Ws[kq + 1][c] = v.y; Ws[kq + 2][c] = v.z; Ws[kq + 3][c] = v.w;
        }
        __syncthreads();
#pragma unroll
        for (int k = 0; k < 32; ++k) {
            const ulonglong2* ap = reinterpret_cast<const ulonglong2*>(&As[k][rr]);
            ulonglong2 a01 = ap[0], a23 = ap[1];
            float4 w4 = *reinterpret_cast<const float4*>(&Ws[k][cc]);
            ull w0 = pack2(w4.x), w1 = pack2(w4.y), w2 = pack2(w4.z), w3 = pack2(w4.w);
            acc[0][0]=ffma2(a01.x,w0,acc[0][0]); acc[0][1]=ffma2(a01.x,w1,acc[0][1]);
            acc[0][2]=ffma2(a01.x,w2,acc[0][2]); acc[0][3]=ffma2(a01.x,w3,acc[0][3]);
            acc[1][0]=ffma2(a01.y,w0,acc[1][0]); acc[1][1]=ffma2(a01.y,w1,acc[1][1]);
            acc[1][2]=ffma2(a01.y,w2,acc[1][2]); acc[1][3]=ffma2(a01.y,w3,acc[1][3]);
            acc[2][0]=ffma2(a23.x,w0,acc[2][0]); acc[2][1]=ffma2(a23.x,w1,acc[2][1]);
            acc[2][2]=ffma2(a23.x,w2,acc[2][2]); acc[2][3]=ffma2(a23.x,w3,acc[2][3]);
            acc[3][0]=ffma2(a23.y,w0,acc[3][0]); acc[3][1]=ffma2(a23.y,w1,acc[3][1]);
            acc[3][2]=ffma2(a23.y,w2,acc[3][2]); acc[3][3]=ffma2(a23.y,w3,acc[3][3]);
        }
    }
    float b0=0.f,b1=0.f,b2=0.f,b3=0.f;
    if (bias) { b0=bias[cc]; b1=bias[cc+1]; b2=bias[cc+2]; b3=bias[cc+3]; }
#pragma unroll
    for (int j = 0; j < 4; ++j) {
        float2 v0=unpack2(acc[j][0]), v1=unpack2(acc[j][1]), v2=unpack2(acc[j][2]), v3=unpack2(acc[j][3]);
        int rowA = r0 + rr + j * 2;
        float4 oA = make_float4(v0.x+b0, v1.x+b1, v2.x+b2, v3.x+b3);
        float4 oB = make_float4(v0.y+b0, v1.y+b1, v2.y+b2, v3.y+b3);
        *reinterpret_cast<float4*>(&C[(size_t)rowA * 128 + cc]) = oA;
        *reinterpret_cast<float4*>(&C[(size_t)(rowA + 1) * 128 + cc]) = oB;
    }
}

__global__ __launch_bounds__(256)
void gemm_init_kernel(const float* __restrict__ bio_a, const float* __restrict__ bio_b,
                      const float* __restrict__ W, const float* __restrict__ bias)
{
    gemm_body<PIN>(blockIdx.z ? bio_b : bio_a, W, bias,
                   blockIdx.z ? &g_x[1][0][0][0] : &g_x[0][0][0][0]);
}

// proj + fused s1/s2 epilogue + permuted xh copy
__global__ __launch_bounds__(256)
void gemm_proj_kernel(const float* __restrict__ W, const float* __restrict__ attw)
{
    int br = blockIdx.z;
    const float* A = br ? &g_x[1][0][0][0] : &g_x[0][0][0][0];
    float* C = br ? &g_xh[1][0][0][0] : &g_xh[0][0][0][0];
    gemm_body<POUT>(A, W, nullptr, C);
    __syncthreads();

    int t = threadIdx.x;
    int row = blockIdx.x * 64 + (t >> 2);
    int h = t & 3;
    const float* xr = &C[(size_t)row * 128 + h * 32];
    const float* w1 = &attw[h * 64];
    int bb = row >> 11, ii = row & 2047;
    float* xp = &g_xhp[br][bb][ii][h * 32];
    float s1 = 0.f, s2 = 0.f;
#pragma unroll
    for (int k = 0; k < 32; k += 4) {
        float4 xv = *reinterpret_cast<const float4*>(&xr[k]);
        float4 a1 = *reinterpret_cast<const float4*>(&w1[k]);
        float4 a2 = *reinterpret_cast<const float4*>(&w1[32 + k]);
        s1 += xv.x*a1.x + xv.y*a1.y + xv.z*a1.z + xv.w*a1.w;
        s2 += xv.x*a2.x + xv.y*a2.y + xv.z*a2.z + xv.w*a2.w;
        // permuted store: source d -> (d&7)*4 + (d>>3)
        xp[((k + 0) & 7) * 4 + ((k + 0) >> 3)] = xv.x;
        xp[((k + 1) & 7) * 4 + ((k + 1) >> 3)] = xv.y;
        xp[((k + 2) & 7) * 4 + ((k + 2) >> 3)] = xv.z;
        xp[((k + 3) & 7) * 4 + ((k + 3) >> 3)] = xv.w;
    }
    g_s1[br][bb][ii][h] = s1;
    g_s2[br][bb][ii][h] = s2;
}

// ---------------- fused GAT attention: warp-mma tf32, streamed adjacency ----------------
// BI=32 rows/block, 8 warps; warp w -> (head h = w&3, row-group g = w>>2).
// xh staged from PERMUTED g_xhp: each lane's 4 B-fragment values per j are one LDS.128.
#define BI 32
#define XHS 136

__global__ __launch_bounds__(256, 4)
void attn_kernel(const int* __restrict__ adjA, const int* __restrict__ adjB,
                 const float* __restrict__ attb)
{
    __shared__ float xh_s[32 * XHS];
    __shared__ float s2_s[32][4];
    __shared__ unsigned adjw[32];

    int t = threadIdx.x, lane = t & 31, w = t >> 5;
    int br = blockIdx.z, b = blockIdx.y;
    int i0 = blockIdx.x * BI;
    const int* adj = (br ? adjB : adjA) + (size_t)b * NN * NN;
    const float4* xh4 = reinterpret_cast<const float4*>(&g_xhp[br][b][0][0]);

    // ---- warp/lane mapping ----
    int h = w & 3, g = w >> 2;
    int r = lane >> 2, c = lane & 3;
    int rowL0 = g * 16 + r, rowL1 = rowL0 + 8;
    float abh = attb[h];
    float s1a = g_s1[br][b][i0 + rowL0][h] + abh;
    float s1b = g_s1[br][b][i0 + rowL1][h] + abh;

    float acc[4][4];
#pragma unroll
    for (int q = 0; q < 4; ++q) { acc[q][0]=0.f; acc[q][1]=0.f; acc[q][2]=0.f; acc[q][3]=0.f; }
    float zacc0 = 0.f, zacc1 = 0.f;

    // ---- adjacency mapping: thread covers (row = t>>3, 4 cols = (t&7)*4..+3) ----
    int arow = t >> 3, aseg = t & 7;
    const int4* aptr = reinterpret_cast<const int4*>(adj + (size_t)(i0 + arow) * NN);

    // ---- prefetch tile 0 ----
    int dd = t & 31, rw = t >> 5;
    float4 r0 = xh4[(size_t)(rw)      * 32 + dd];
    float4 r1 = xh4[(size_t)(rw + 8)  * 32 + dd];
    float4 r2 = xh4[(size_t)(rw + 16) * 32 + dd];
    float4 r3 = xh4[(size_t)(rw + 24) * 32 + dd];
    int4 a4 = aptr[aseg];
    float4 s2r = make_float4(0.f, 0.f, 0.f, 0.f);
    if (t < 32) s2r = *reinterpret_cast<const float4*>(&g_s2[br][b][t][0]);

    for (int jt = 0; jt < NN / 32; ++jt) {
        __syncthreads();   // buffers free
        // stage xh (row-linear copy; permutation already baked into g_xhp)
        *reinterpret_cast<float4*>(&xh_s[(rw)      * XHS + dd * 4]) = r0;
        *reinterpret_cast<float4*>(&xh_s[(rw + 8)  * XHS + dd * 4]) = r1;
        *reinterpret_cast<float4*>(&xh_s[(rw + 16) * XHS + dd * 4]) = r2;
        *reinterpret_cast<float4*>(&xh_s[(rw + 24) * XHS + dd * 4]) = r3;
        if (t < 32) *reinterpret_cast<float4*>(&s2_s[t][0]) = s2r;
        // pack adjacency word for this tile (8 lanes per row share via shfl-OR)
        {
            unsigned nib = (unsigned)(a4.x != 0) | ((unsigned)(a4.y != 0) << 1)
                         | ((unsigned)(a4.z != 0) << 2) | ((unsigned)(a4.w != 0) << 3);
            unsigned word = nib << (aseg * 4);
            word |= __shfl_xor_sync(0xffffffffu, word, 1);
            word |= __shfl_xor_sync(0xffffffffu, word, 2);
            word |= __shfl_xor_sync(0xffffffffu, word, 4);
            if (aseg == 0) adjw[arow] = word;
        }
        // prefetch tile jt+1
        if (jt + 1 < NN / 32) {
            size_t base = (size_t)(jt + 1) * 1024;
            r0 = xh4[base + (size_t)(rw)      * 32 + dd];
            r1 = xh4[base + (size_t)(rw + 8)  * 32 + dd];
            r2 = xh4[base + (size_t)(rw + 16) * 32 + dd];
            r3 = xh4[base + (size_t)(rw + 24) * 32 + dd];
            a4 = aptr[(jt + 1) * 8 + aseg];
            if (t < 32) s2r = *reinterpret_cast<const float4*>(&g_s2[br][b][(jt + 1) * 32 + t][0]);
        }
        __syncthreads();   // tile ready

        unsigned bA = adjw[rowL0];
        unsigned bB = adjw[rowL1];
#pragma unroll
        for (int ks = 0; ks < 4; ++ks) {
            int j0 = ks * 8 + c, j1 = j0 + 4;
            float s20 = s2_s[j0][h], s21 = s2_s[j1][h];
            float a0 = 0.f, a1 = 0.f, a2 = 0.f, a3 = 0.f;
            if ((bA >> j0) & 1u) { float v = s1a + s20; a0 = __expf(fmaxf(v, 0.2f * v)); }
            if ((bB >> j0) & 1u) { float v = s1b + s20; a1 = __expf(fmaxf(v, 0.2f * v)); }
            if ((bA >> j1) & 1u) { float v = s1a + s21; a2 = __expf(fmaxf(v, 0.2f * v)); }
            if ((bB >> j1) & 1u) { float v = s1b + s21; a3 = __expf(fmaxf(v, 0.2f * v)); }
            zacc0 += a0 + a2;
            zacc1 += a1 + a3;
            float4 x0q = *reinterpret_cast<const float4*>(&xh_s[j0 * XHS + h * 32 + r * 4]);
            float4 x1q = *reinterpret_cast<const float4*>(&xh_s[j1 * XHS + h * 32 + r * 4]);
            mma1688(acc[0], a0, a1, a2, a3, x0q.x, x1q.x);
            mma1688(acc[1], a0, a1, a2, a3, x0q.y, x1q.y);
            mma1688(acc[2], a0, a1, a2, a3, x0q.z, x1q.z);
            mma1688(acc[3], a0, a1, a2, a3, x0q.w, x1q.w);
        }
    }

    // ---- Z quad-reduce ----
    zacc0 += __shfl_xor_sync(0xffffffffu, zacc0, 1);
    zacc0 += __shfl_xor_sync(0xffffffffu, zacc0, 2);
    zacc1 += __shfl_xor_sync(0xffffffffu, zacc1, 1);
    zacc1 += __shfl_xor_sync(0xffffffffu, zacc1, 2);
    float iz0 = 1.0f / ((zacc0 == 0.f) ? 1.f : zacc0);
    float iz1 = 1.0f / ((zacc1 == 0.f) ? 1.f : zacc1);

    int gr0 = i0 + rowL0, gr1 = i0 + rowL1;
#pragma unroll
    for (int ng = 0; ng < 4; ++ng) {
        int d = h * 32 + ng * 8 + 2 * c;
        float2 x0 = *reinterpret_cast<const float2*>(&g_x[br][b][gr0][d]);
        float2 x1 = *reinterpret_cast<const float2*>(&g_x[br][b][gr1][d]);
        float2 o0, o1;
        o0.x = fmaxf(acc[ng][0] * iz0, 0.f) + x0.x;
        o0.y = fmaxf(acc[ng][1] * iz0, 0.f) + x0.y;
        o1.x = fmaxf(acc[ng][2] * iz1, 0.f) + x1.x;
        o1.y = fmaxf(acc[ng][3] * iz1, 0.f) + x1.y;
        *reinterpret_cast<float2*>(&g_G[br][b][gr0][d]) = o0;
        *reinterpret_cast<float2*>(&g_G[br][b][gr1][d]) = o1;
    }
}

// ---------------- GGE MLP ----------------
__global__ __launch_bounds__(512)
void gge_kernel(const float* __restrict__ a_in, const float* __restrict__ b_in,
                const float* __restrict__ W1, const float* __restrict__ b1,
                const float* __restrict__ W2, const float* __restrict__ b2)
{
    int br = blockIdx.x, bb = blockIdx.y;
    const float* in = (br ? b_in : a_in) + (size_t)bb * FIN;
    __shared__ float a_s[FIN];
    __shared__ float part[4][128];
    __shared__ float h1[128];
    int t = threadIdx.x;
    if (t < FIN) a_s[t] = in[t];
    __syncthreads();
    int d = t & 127, g = t >> 7;
    float acc = 0.f;
#pragma unroll 8
    for (int k = g * 128; k < g * 128 + 128; k += 4) {
        float4 w = *reinterpret_cast<const float4*>(&W1[(size_t)d * FIN + k]);
        acc += a_s[k]*w.x + a_s[k+1]*w.y + a_s[k+2]*w.z + a_s[k+3]*w.w;
    }
    part[g][d] = acc;
    __syncthreads();
    if (t < 128) h1[t] = fmaxf(part[0][t]+part[1][t]+part[2][t]+part[3][t] + b1[t], 0.f);
    __syncthreads();
    float acc2 = 0.f;
#pragma unroll 8
    for (int k = g * 32; k < g * 32 + 32; k += 4) {
        float4 w = *reinterpret_cast<const float4*>(&W2[(size_t)d * 128 + k]);
        acc2 += h1[k]*w.x + h1[k+1]*w.y + h1[k+2]*w.z + h1[k+3]*w.w;
    }
    part[g][d] = acc2;
    __syncthreads();
    if (t < 128) g_h[br][bb][t] = fmaxf(part[0][t]+part[1][t]+part[2][t]+part[3][t] + b2[t], 0.f);
}

// ---------------- GAGA partials: grid (8 chunks, NB, 2) ----------------
__global__ __launch_bounds__(256)
void gaga_part_kernel()
{
    int chunk = blockIdx.x, b = blockIdx.y, br = blockIdx.z;
    const float4* G4 = reinterpret_cast<const float4*>(&g_G[br][b][0][0]);
    __shared__ float h_s[128];
    __shared__ float e_s[256];
    __shared__ float pr[8][132];
    int t = threadIdx.x, lane = t & 31, w = t >> 5;
    if (t < 128) h_s[t] = g_h[br][b][t];
    __syncthreads();
    int n0 = chunk * 256;
    float4 hv = *reinterpret_cast<const float4*>(&h_s[lane * 4]);

    for (int i = 0; i < 16; ++i) {
        int na = n0 + w * 32 + i, nb = na + 16;
        float4 ga = G4[(size_t)na * 32 + lane];
        float4 gb = G4[(size_t)nb * 32 + lane];
        float va = ga.x*hv.x + ga.y*hv.y + ga.z*hv.z + ga.w*hv.w;
        float vb = gb.x*hv.x + gb.y*hv.y + gb.z*hv.z + gb.w*hv.w;
#pragma unroll
        for (int s = 16; s > 0; s >>= 1) {
            va += __shfl_xor_sync(0xffffffffu, va, s);
            vb += __shfl_xor_sync(0xffffffffu, vb, s);
        }
        if (lane == 0) {
            e_s[w * 32 + i]      = __expf(va);
            e_s[w * 32 + i + 16] = __expf(vb);
        }
    }
    __syncthreads();

    int d4 = t & 31, rg = t >> 5;
    float4 acc = make_float4(0.f, 0.f, 0.f, 0.f);
    float zp = 0.f;
#pragma unroll 4
    for (int i = 0; i < 32; ++i) {
        int n = n0 + rg * 32 + i;
        float e = e_s[rg * 32 + i];
        float4 gv = G4[(size_t)n * 32 + d4];
        acc.x += e * gv.x; acc.y += e * gv.y; acc.z += e * gv.z; acc.w += e * gv.w;
        zp += e;
    }
    *reinterpret_cast<float4*>(&pr[rg][d4 * 4]) = acc;
    if (d4 == 0) pr[rg][128] = zp;
    __syncthreads();
    if (t < 128) {
        float s = 0.f;
#pragma unroll
        for (int q = 0; q < 8; ++q) s += pr[q][t];
        g_gpart[br][b][chunk][t] = s;
    } else if (t == 128) {
        float z = 0.f;
#pragma unroll
        for (int q = 0; q < 8; ++q) z += pr[q][128];
        g_gpart[br][b][chunk][128] = z;
    }
}

// ---------------- LED head + gaga combine + log_softmax ----------------
__global__ __launch_bounds__(1024)
void led_kernel(const float* __restrict__ convW, const float* __restrict__ convb,
                const float* __restrict__ W1, const float* __restrict__ b1,
                const float* __restrict__ W2, const float* __restrict__ b2,
                float* __restrict__ out)
{
    __shared__ float ea[NB * 256], eb[NB * 256];
    __shared__ float feat[NB * 512];
    __shared__ float part2[2][NB * 128];
    __shared__ float x1[NB * 128];
    __shared__ float lg[NB * 2];
    int t = threadIdx.x;

    {
        int br2 = t >> 9, bb = (t >> 7) & 3, d = t & 127;
        float sv = 0.f, zv = 0.f;
#pragma unroll
        for (int c2 = 0; c2 < 8; ++c2) {
            sv += g_gpart[br2][bb][c2][d];
            zv += g_gpart[br2][bb][c2][128];
        }
        float gv = sv / zv;
        float hv = g_h[br2][bb][d];
        if (br2 == 0) { ea[bb * 256 + d] = hv; ea[bb * 256 + 128 + d] = gv; }
        else          { eb[bb * 256 + d] = hv; eb[bb * 256 + 128 + d] = gv; }
    }
    __syncthreads();

    if (t < NB * 256) {
        int bb = t >> 8, o = t & 255;
        float sa = 0.f, sb = 0.f;
#pragma unroll 8
        for (int k = 0; k < 256; k += 4) {
            float4 w = *reinterpret_cast<const float4*>(&convW[(size_t)o * 256 + k]);
            sa += ea[bb*256+k]*w.x + ea[bb*256+k+1]*w.y + ea[bb*256+k+2]*w.z + ea[bb*256+k+3]*w.w;
            sb += eb[bb*256+k]*w.x + eb[bb*256+k+1]*w.y + eb[bb*256+k+2]*w.z + eb[bb*256+k+3]*w.w;
        }
        feat[bb * 512 + o]       = fmaxf(sa, sb) + convb[o];
        feat[bb * 512 + 256 + o] = ea[bb * 256 + o] - eb[bb * 256 + o];
    }
    __syncthreads();

    {
        int g = t >> 9, idx = t & 511;
        int bb = idx >> 7, d = idx & 127;
        float acc = 0.f;
#pragma unroll 8
        for (int k = g * 256; k < g * 256 + 256; k += 4) {
            float4 w = *reinterpret_cast<const float4*>(&W1[(size_t)d * 512 + k]);
            acc += feat[bb*512+k]*w.x + feat[bb*512+k+1]*w.y + feat[bb*512+k+2]*w.z + feat[bb*512+k+3]*w.w;
        }
        part2[g][idx] = acc;
    }
    __syncthreads();
    if (t < 512) {
        int d = t & 127;
        x1[t] = fmaxf(part2[0][t] + part2[1][t] + b1[d], 0.f);
    }
    __syncthreads();

    if (t < NB * 2) {
        int bb = t >> 1, c = t & 1;
        float acc = b2[c];
        for (int k = 0; k < 128; ++k) acc += x1[bb * 128 + k] * W2[c * 128 + k];
        lg[bb * 2 + c] = acc;
    }
    __syncthreads();
    if (t < NB) {
        float l0 = lg[t * 2], l1 = lg[t * 2 + 1];
        float m = fmaxf(l0, l1);
        float lse = m + logf(expf(l0 - m) + expf(l1 - m));
        out[t * 2]     = l0 - lse;
        out[t * 2 + 1] = l1 - lse;
    }
}

// ---------------- host ----------------
extern "C" void kernel_launch(void* const* d_in, const int* in_sizes, int n_in,
                              void* d_out, int out_size)
{
    const float* a      = (const float*)d_in[0];
    const float* bio_a  = (const float*)d_in[1];
    const int*   A      = (const int*)  d_in[2];
    const float* b      = (const float*)d_in[3];
    const float* bio_b  = (const float*)d_in[4];
    const int*   B      = (const int*)  d_in[5];
    const float* initW  = (const float*)d_in[6];
    const float* initb  = (const float*)d_in[7];
    const float* projW  = (const float*)d_in[8];
    const float* attw   = (const float*)d_in[9];
    const float* attb   = (const float*)d_in[10];
    const float* ggeW1  = (const float*)d_in[11];
    const float* ggeb1  = (const float*)d_in[12];
    const float* ggeW2  = (const float*)d_in[13];
    const float* ggeb2  = (const float*)d_in[14];
    const float* convW  = (const float*)d_in[15];
    const float* convb  = (const float*)d_in[16];
    const float* ledW1  = (const float*)d_in[17];
    const float* ledb1  = (const float*)d_in[18];
    const float* ledW2  = (const float*)d_in[19];
    const float* ledb2  = (const float*)d_in[20];
    float* out = (float*)d_out;

    dim3 gGemm(NB * NN / 64, 1, 2);
    gemm_init_kernel<<<gGemm, 256>>>(bio_a, bio_b, initW, initb);
    gemm_proj_kernel<<<gGemm, 256>>>(projW, attw);

    dim3 gGge(2, NB);
    gge_kernel<<<gGge, 512>>>(a, b, ggeW1, ggeb1, ggeW2, ggeb2);

    dim3 gAttn(NN / BI, NB, 2);   // 4th launch: profiled slot
    attn_kernel<<<gAttn, 256>>>(A, B, attb);

    dim3 gGaga(8, NB, 2);
    gaga_part_kernel<<<gGaga, 256>>>();

    led_kernel<<<1, 1024>>>(convW, convb, ledW1, ledb1, ledW2, ledb2, out);
}